// round 3
// baseline (speedup 1.0000x reference)
#include <cuda_runtime.h>
#include <cuda_bf16.h>
#include <cstdint>

#define NMAX 100000

// Scratch (static device globals — allocation-free per harness rules)
__device__ __align__(16) float g_ylr[NMAX * 128];  // projected [y_l | y_r], node-major
__device__ __align__(16) float g_agg[NMAX * 64];   // aggregation accumulator
__device__ __align__(16) float g_x[NMAX * 64];     // layer activations
__device__ __align__(16) float g_deg[NMAX];        // in-degree (float count)

// ---------------------------------------------------------------------------
// cp.async helpers
// ---------------------------------------------------------------------------
__device__ __forceinline__ void cp_async16(uint32_t dst, const void* src, int src_bytes) {
    asm volatile("cp.async.cg.shared.global [%0], [%1], 16, %2;\n"
                 :: "r"(dst), "l"(src), "r"(src_bytes));
}
__device__ __forceinline__ void cp_commit() { asm volatile("cp.async.commit_group;\n"); }
template <int N>
__device__ __forceinline__ void cp_wait() { asm volatile("cp.async.wait_group %0;\n" :: "n"(N)); }

// packed f32x2 fma: acc = a2 * b2 + acc   (per-half IEEE fp32 fma)
__device__ __forceinline__ void fma_x2(unsigned long long& acc, unsigned long long a2,
                                       unsigned long long b2) {
    asm("fma.rn.f32x2 %0, %1, %2, %0;" : "+l"(acc) : "l"(a2), "l"(b2));
}
__device__ __forceinline__ unsigned long long dup_f32(float a) {
    unsigned long long r;
    asm("mov.b64 %0, {%1, %1};" : "=l"(r) : "f"(a));
    return r;
}

// ---------------------------------------------------------------------------
// zero
// ---------------------------------------------------------------------------
__global__ void zero_kernel(float* __restrict__ p, int count) {
    int i = blockIdx.x * blockDim.x + threadIdx.x;
    int n4 = count >> 2;
    float4* p4 = reinterpret_cast<float4*>(p);
    float4 z = make_float4(0.f, 0.f, 0.f, 0.f);
    for (int j = i; j < n4; j += gridDim.x * blockDim.x) p4[j] = z;
    if (i == 0) {
        for (int j = n4 * 4; j < count; ++j) p[j] = 0.f;
    }
}

// ---------------------------------------------------------------------------
// degree
// ---------------------------------------------------------------------------
__global__ void deg_kernel(const int* __restrict__ dst, float* __restrict__ deg, int E) {
    int i = blockIdx.x * blockDim.x + threadIdx.x;
    if (i < E) atomicAdd(&deg[dst[i]], 1.0f);
}

// ---------------------------------------------------------------------------
// projection GEMM (packed f32x2): ylr[n x NC] = x[n x K] @ [wl | wr]
// BK-tiled cp.async double-buffered. TM=8 rows, TN=8 cols per thread:
// two float4 col groups at jA and jA+F; B operand pairs loaded directly as
// u64 pairs (ld.shared.v2.u64); A scalar broadcast duplicated via mov.b64.
// ---------------------------------------------------------------------------
template <int K, int NC, int BM, int BK>
__global__ void __launch_bounds__((BM / 8) * (NC / 8), 2)
sgemm_proj_x2(const float* __restrict__ x, const float* __restrict__ wl,
              const float* __restrict__ wr, float* __restrict__ ylr, int n) {
    constexpr int TM = 8;
    constexpr int PAD = 4;
    constexpr int F = NC / 2;
    constexpr int NTH = (BM / TM) * (NC / 8);
    constexpr int KT = K / BK;
    constexpr int XS = BK + PAD;

    extern __shared__ float sm[];
    float* sX = sm;                    // [2][BM * XS]
    float* sB = sm + 2 * BM * XS;      // [2][BK * NC]

    const int tid = threadIdx.x;
    const int nb = blockIdx.x * BM;
    const int mrem = n - nb;

    auto load_tile = [&](int kb, int buf) {
        const int k0 = kb * BK;
        float* sXb = sX + buf * BM * XS;
        float* sBb = sB + buf * BK * NC;
        // X tile: BM x BK
        for (int idx = tid; idx < BM * BK / 4; idx += NTH) {
            int m = idx / (BK / 4);
            int kc = idx % (BK / 4);
            uint32_t dst = (uint32_t)__cvta_generic_to_shared(&sXb[m * XS + kc * 4]);
            int mm = (m < mrem) ? m : 0;
            const float* src = x + (size_t)(nb + mm) * K + k0 + kc * 4;
            cp_async16(dst, src, (m < mrem) ? 16 : 0);
        }
        // W tile: BK x NC  (cols [0,F) from wl, [F,NC) from wr)
        for (int idx = tid; idx < BK * NC / 4; idx += NTH) {
            int kr = idx / (NC / 4);
            int j = (idx % (NC / 4)) * 4;
            const float* src = (j < F) ? (wl + (size_t)(kr + k0) * F + j)
                                       : (wr + (size_t)(kr + k0) * F + (j - F));
            uint32_t dst = (uint32_t)__cvta_generic_to_shared(&sBb[kr * NC + j]);
            cp_async16(dst, src, 16);
        }
    };

    load_tile(0, 0);
    cp_commit();

    constexpr int CG = NC / 8;
    const int tj = tid % CG;
    const int ti = tid / CG;
    const int m0 = ti * TM;
    const int jA = tj * 4;
    const int jB = jA + F;

    unsigned long long acc[TM][4];
#pragma unroll
    for (int i = 0; i < TM; ++i)
#pragma unroll
        for (int t = 0; t < 4; ++t) acc[i][t] = 0ull;

    for (int kb = 0; kb < KT; ++kb) {
        if (kb + 1 < KT) {
            load_tile(kb + 1, (kb + 1) & 1);
            cp_commit();
            cp_wait<1>();
        } else {
            cp_wait<0>();
        }
        __syncthreads();

        const float* bx = sX + (kb & 1) * BM * XS;
        const float* bb = sB + (kb & 1) * BK * NC;
#pragma unroll
        for (int k = 0; k < BK; ++k) {
            ulonglong2 bp0 = *reinterpret_cast<const ulonglong2*>(&bb[k * NC + jA]);
            ulonglong2 bp1 = *reinterpret_cast<const ulonglong2*>(&bb[k * NC + jB]);
#pragma unroll
            for (int i = 0; i < TM; ++i) {
                unsigned long long a2 = dup_f32(bx[(m0 + i) * XS + k]);
                fma_x2(acc[i][0], a2, bp0.x);
                fma_x2(acc[i][1], a2, bp0.y);
                fma_x2(acc[i][2], a2, bp1.x);
                fma_x2(acc[i][3], a2, bp1.y);
            }
        }
        __syncthreads();
    }

#pragma unroll
    for (int i = 0; i < TM; ++i) {
        int node = nb + m0 + i;
        if (node < n) {
            ulonglong2 v0, v1;
            v0.x = acc[i][0]; v0.y = acc[i][1];
            v1.x = acc[i][2]; v1.y = acc[i][3];
            *reinterpret_cast<ulonglong2*>(&ylr[(size_t)node * NC + jA]) = v0;
            *reinterpret_cast<ulonglong2*>(&ylr[(size_t)node * NC + jB]) = v1;
        }
    }
}

// ---------------------------------------------------------------------------
// layer 3 projection (Fin=16, Fout=9): per-node kernel, stride 18
// ---------------------------------------------------------------------------
__global__ void proj3_kernel(const float* __restrict__ x, const float* __restrict__ wl,
                             const float* __restrict__ wr, float* __restrict__ ylr, int n) {
    __shared__ float swl[16 * 9];
    __shared__ float swr[16 * 9];
    for (int i = threadIdx.x; i < 144; i += blockDim.x) {
        swl[i] = wl[i];
        swr[i] = wr[i];
    }
    __syncthreads();

    int node = blockIdx.x * blockDim.x + threadIdx.x;
    if (node >= n) return;

    float xv[16];
    const float4* xr = reinterpret_cast<const float4*>(x + (size_t)node * 16);
#pragma unroll
    for (int c = 0; c < 4; ++c) {
        float4 v = xr[c];
        xv[c * 4 + 0] = v.x; xv[c * 4 + 1] = v.y; xv[c * 4 + 2] = v.z; xv[c * 4 + 3] = v.w;
    }
#pragma unroll
    for (int j = 0; j < 9; ++j) {
        float al = 0.f, ar = 0.f;
#pragma unroll
        for (int k = 0; k < 16; ++k) {
            al = fmaf(xv[k], swl[k * 9 + j], al);
            ar = fmaf(xv[k], swr[k * 9 + j], ar);
        }
        ylr[(size_t)node * 18 + j] = al;
        ylr[(size_t)node * 18 + 9 + j] = ar;
    }
}

// ---------------------------------------------------------------------------
// scatter: agg[dst] += y_l[src]   (vec4 reduction, F % 4 == 0)
// ---------------------------------------------------------------------------
template <int F>
__global__ void scatter_kernel(const float* __restrict__ ylr, const int* __restrict__ src,
                               const int* __restrict__ dst, float* __restrict__ agg, int E) {
    constexpr int CH = F / 4;
    int idx = blockIdx.x * blockDim.x + threadIdx.x;
    if (idx >= E * CH) return;
    int e = idx / CH, c = idx % CH;
    int s = __ldg(src + e), d = __ldg(dst + e);
    float4 v = reinterpret_cast<const float4*>(ylr)[(size_t)s * (2 * F / 4) + c];
    float* addr = agg + (size_t)d * F + c * 4;
    asm volatile("red.global.add.v4.f32 [%0], {%1, %2, %3, %4};"
                 :: "l"(addr), "f"(v.x), "f"(v.y), "f"(v.z), "f"(v.w)
                 : "memory");
}

__global__ void scatter9_kernel(const float* __restrict__ ylr, const int* __restrict__ src,
                                const int* __restrict__ dst, float* __restrict__ agg, int E) {
    int idx = blockIdx.x * blockDim.x + threadIdx.x;
    if (idx >= E * 9) return;
    int e = idx / 9, c = idx % 9;
    int s = __ldg(src + e), d = __ldg(dst + e);
    atomicAdd(agg + (size_t)d * 9 + c, ylr[(size_t)s * 18 + c]);
}

// ---------------------------------------------------------------------------
// combine: out = [relu]( agg/deg + y_r + b ); also re-zeroes agg for the
// next layer's scatter (next width is always <= this width).
// ---------------------------------------------------------------------------
template <int F, bool RELU>
__global__ void combine_kernel(float* __restrict__ agg, const float* __restrict__ ylr,
                               const float* __restrict__ bias, const float* __restrict__ deg,
                               float* __restrict__ out, int n) {
    constexpr int CH = F / 4;
    int idx = blockIdx.x * blockDim.x + threadIdx.x;
    if (idx >= n * CH) return;
    int node = idx / CH, c = idx % CH;
    float iv = __frcp_rn(fmaxf(__ldg(deg + node), 1.0f));
    float4 a = reinterpret_cast<const float4*>(agg)[(size_t)node * CH + c];
    reinterpret_cast<float4*>(agg)[(size_t)node * CH + c] = make_float4(0.f, 0.f, 0.f, 0.f);
    float4 r = reinterpret_cast<const float4*>(ylr)[(size_t)node * (2 * CH) + CH + c];
    float4 b = reinterpret_cast<const float4*>(bias)[c];
    float4 v;
    v.x = fmaf(a.x, iv, r.x) + b.x;
    v.y = fmaf(a.y, iv, r.y) + b.y;
    v.z = fmaf(a.z, iv, r.z) + b.z;
    v.w = fmaf(a.w, iv, r.w) + b.w;
    if (RELU) {
        v.x = fmaxf(v.x, 0.f); v.y = fmaxf(v.y, 0.f);
        v.z = fmaxf(v.z, 0.f); v.w = fmaxf(v.w, 0.f);
    }
    reinterpret_cast<float4*>(out)[(size_t)node * CH + c] = v;
}

__global__ void combine9_kernel(const float* __restrict__ agg, const float* __restrict__ ylr,
                                const float* __restrict__ bias, const float* __restrict__ deg,
                                float* __restrict__ out, int n) {
    int idx = blockIdx.x * blockDim.x + threadIdx.x;
    if (idx >= n * 9) return;
    int node = idx / 9, j = idx % 9;
    float iv = __frcp_rn(fmaxf(__ldg(deg + node), 1.0f));
    float v = fmaf(agg[(size_t)node * 9 + j], iv, ylr[(size_t)node * 18 + 9 + j]) + __ldg(bias + j);
    out[(size_t)node * 9 + j] = v;
}

// ---------------------------------------------------------------------------
// launch
// ---------------------------------------------------------------------------
extern "C" void kernel_launch(void* const* d_in, const int* in_sizes, int n_in,
                              void* d_out, int out_size) {
    const float* emb = (const float*)d_in[0];
    const int* ei = (const int*)d_in[1];
    // d_in[2] = edge_attr, unused by SAGEConv
    const float* wl0 = (const float*)d_in[3];
    const float* wr0 = (const float*)d_in[4];
    const float* b0  = (const float*)d_in[5];
    const float* wl1 = (const float*)d_in[6];
    const float* wr1 = (const float*)d_in[7];
    const float* b1  = (const float*)d_in[8];
    const float* wl2 = (const float*)d_in[9];
    const float* wr2 = (const float*)d_in[10];
    const float* b2  = (const float*)d_in[11];
    const float* wl3 = (const float*)d_in[12];
    const float* wr3 = (const float*)d_in[13];
    const float* b3  = (const float*)d_in[14];
    float* out = (float*)d_out;

    const int n = in_sizes[0] / 128;
    const int E = in_sizes[1] / 2;
    const int* src = ei;
    const int* dst = ei + E;

    float *ylr, *agg, *xbuf, *deg;
    cudaGetSymbolAddress((void**)&ylr, g_ylr);
    cudaGetSymbolAddress((void**)&agg, g_agg);
    cudaGetSymbolAddress((void**)&xbuf, g_x);
    cudaGetSymbolAddress((void**)&deg, g_deg);

    const int TB = 256;
    auto cdiv = [](int a, int b) { return (a + b - 1) / b; };

    // smem: sX[2][BM*(BK+4)] + sB[2][BK*NC]
    const int SM0 = (2 * 128 * 36 + 2 * 32 * 128) * 4;  // 69632
    const int SM1 = (2 * 128 * 36 + 2 * 32 * 64) * 4;   // 53248
    const int SM2 = (2 * 256 * 36 + 2 * 32 * 32) * 4;   // 81920
    cudaFuncSetAttribute((const void*)sgemm_proj_x2<128, 128, 128, 32>,
                         cudaFuncAttributeMaxDynamicSharedMemorySize, SM0);
    cudaFuncSetAttribute((const void*)sgemm_proj_x2<64, 64, 128, 32>,
                         cudaFuncAttributeMaxDynamicSharedMemorySize, SM1);
    cudaFuncSetAttribute((const void*)sgemm_proj_x2<32, 32, 256, 32>,
                         cudaFuncAttributeMaxDynamicSharedMemorySize, SM2);

    // degree + initial agg zero (combine kernels re-zero for later layers)
    zero_kernel<<<256, TB>>>(deg, n);
    deg_kernel<<<cdiv(E, TB), TB>>>(dst, deg, E);
    zero_kernel<<<512, TB>>>(agg, n * 64);

    // ---- layer 0: 128 -> 64, relu ----
    sgemm_proj_x2<128, 128, 128, 32><<<cdiv(n, 128), 256, SM0>>>(emb, wl0, wr0, ylr, n);
    scatter_kernel<64><<<cdiv(E * 16, TB), TB>>>(ylr, src, dst, agg, E);
    combine_kernel<64, true><<<cdiv(n * 16, TB), TB>>>(agg, ylr, b0, deg, xbuf, n);

    // ---- layer 1: 64 -> 32, relu ----
    sgemm_proj_x2<64, 64, 128, 32><<<cdiv(n, 128), 128, SM1>>>(xbuf, wl1, wr1, ylr, n);
    scatter_kernel<32><<<cdiv(E * 8, TB), TB>>>(ylr, src, dst, agg, E);
    combine_kernel<32, true><<<cdiv(n * 8, TB), TB>>>(agg, ylr, b1, deg, xbuf, n);

    // ---- layer 2: 32 -> 16, relu ----
    sgemm_proj_x2<32, 32, 256, 32><<<cdiv(n, 256), 128, SM2>>>(xbuf, wl2, wr2, ylr, n);
    scatter_kernel<16><<<cdiv(E * 4, TB), TB>>>(ylr, src, dst, agg, E);
    combine_kernel<16, true><<<cdiv(n * 4, TB), TB>>>(agg, ylr, b2, deg, xbuf, n);

    // ---- layer 3: 16 -> 9, no relu, write d_out ----
    proj3_kernel<<<cdiv(n, 128), 128>>>(xbuf, wl3, wr3, ylr, n);
    scatter9_kernel<<<cdiv(E * 9, TB), TB>>>(ylr, src, dst, agg, E);
    combine9_kernel<<<cdiv(n * 9, TB), TB>>>(agg, ylr, b3, deg, out, n);
}

// round 4
// speedup vs baseline: 1.1543x; 1.1543x over previous
#include <cuda_runtime.h>
#include <cstdint>

#define NMAX 100000
#define EMAX 600000

// Scratch (static device globals — allocation-free per harness rules)
__device__ __align__(16) float g_ylr[NMAX * 128];  // projected [y_l | y_r]
__device__ __align__(16) float g_x[NMAX * 64];     // layer activations
__device__ int g_cnt[NMAX];    // in-degree
__device__ int g_off[NMAX];    // CSR offsets (exclusive scan of cnt)
__device__ int g_cur[NMAX];    // fill cursors
__device__ int g_esrc[EMAX];   // src node per edge, sorted by dst
__device__ int g_bsum[512];    // scan block sums

// ---------------------------------------------------------------------------
// cp.async + packed fma helpers
// ---------------------------------------------------------------------------
__device__ __forceinline__ void cp_async16(uint32_t dst, const void* src, int src_bytes) {
    asm volatile("cp.async.cg.shared.global [%0], [%1], 16, %2;\n"
                 :: "r"(dst), "l"(src), "r"(src_bytes));
}
__device__ __forceinline__ void cp_commit() { asm volatile("cp.async.commit_group;\n"); }
template <int N>
__device__ __forceinline__ void cp_wait() { asm volatile("cp.async.wait_group %0;\n" :: "n"(N)); }

__device__ __forceinline__ void fma_x2(unsigned long long& acc, unsigned long long a2,
                                       unsigned long long b2) {
    asm("fma.rn.f32x2 %0, %1, %2, %0;" : "+l"(acc) : "l"(a2), "l"(b2));
}
__device__ __forceinline__ unsigned long long dup_f32(float a) {
    unsigned long long r;
    asm("mov.b64 %0, {%1, %1};" : "=l"(r) : "f"(a));
    return r;
}

// ---------------------------------------------------------------------------
// CSR build: hist -> block scan -> sums scan -> add+cursor -> fill
// ---------------------------------------------------------------------------
__global__ void zero_int(int* __restrict__ p, int n) {
    int i = blockIdx.x * blockDim.x + threadIdx.x;
    if (i < n) p[i] = 0;
}

__global__ void hist_kernel(const int* __restrict__ dst, int* __restrict__ cnt, int E) {
    int i = blockIdx.x * blockDim.x + threadIdx.x;
    if (i < E) atomicAdd(&cnt[dst[i]], 1);
}

__global__ void scan_block(const int* __restrict__ cnt, int* __restrict__ off,
                           int* __restrict__ bsum, int n) {
    __shared__ int s[512];
    int i = blockIdx.x * 512 + threadIdx.x;
    int v = (i < n) ? cnt[i] : 0;
    s[threadIdx.x] = v;
    __syncthreads();
#pragma unroll
    for (int st = 1; st < 512; st <<= 1) {
        int t = (threadIdx.x >= st) ? s[threadIdx.x - st] : 0;
        __syncthreads();
        s[threadIdx.x] += t;
        __syncthreads();
    }
    if (i < n) off[i] = s[threadIdx.x] - v;  // exclusive
    if (threadIdx.x == 511) bsum[blockIdx.x] = s[511];
}

__global__ void scan_sums(int* __restrict__ bsum, int nb) {
    __shared__ int s[512];
    int v = (threadIdx.x < nb) ? bsum[threadIdx.x] : 0;
    s[threadIdx.x] = v;
    __syncthreads();
#pragma unroll
    for (int st = 1; st < 512; st <<= 1) {
        int t = (threadIdx.x >= st) ? s[threadIdx.x - st] : 0;
        __syncthreads();
        s[threadIdx.x] += t;
        __syncthreads();
    }
    if (threadIdx.x < nb) bsum[threadIdx.x] = s[threadIdx.x] - v;  // exclusive
}

__global__ void scan_add(int* __restrict__ off, const int* __restrict__ bsum,
                         int* __restrict__ cur, int n) {
    int i = blockIdx.x * 512 + threadIdx.x;
    if (i < n) {
        int o = off[i] + bsum[blockIdx.x];
        off[i] = o;
        cur[i] = o;
    }
}

__global__ void fill_kernel(const int* __restrict__ src, const int* __restrict__ dst,
                            int* __restrict__ cur, int* __restrict__ esrc, int E) {
    int e = blockIdx.x * blockDim.x + threadIdx.x;
    if (e < E) {
        int p = atomicAdd(&cur[dst[e]], 1);
        esrc[p] = src[e];
    }
}

// ---------------------------------------------------------------------------
// projection GEMM (packed f32x2): ylr[n x NC] = x[n x K] @ [wl | wr]
// ---------------------------------------------------------------------------
template <int K, int NC, int BM, int BK>
__global__ void __launch_bounds__((BM / 8) * (NC / 8), 2)
sgemm_proj_x2(const float* __restrict__ x, const float* __restrict__ wl,
              const float* __restrict__ wr, float* __restrict__ ylr, int n) {
    constexpr int TM = 8;
    constexpr int PAD = 4;
    constexpr int F = NC / 2;
    constexpr int NTH = (BM / TM) * (NC / 8);
    constexpr int KT = K / BK;
    constexpr int XS = BK + PAD;

    extern __shared__ float sm[];
    float* sX = sm;                    // [2][BM * XS]
    float* sB = sm + 2 * BM * XS;      // [2][BK * NC]

    const int tid = threadIdx.x;
    const int nb = blockIdx.x * BM;
    const int mrem = n - nb;

    auto load_tile = [&](int kb, int buf) {
        const int k0 = kb * BK;
        float* sXb = sX + buf * BM * XS;
        float* sBb = sB + buf * BK * NC;
        for (int idx = tid; idx < BM * BK / 4; idx += NTH) {
            int m = idx / (BK / 4);
            int kc = idx % (BK / 4);
            uint32_t dst = (uint32_t)__cvta_generic_to_shared(&sXb[m * XS + kc * 4]);
            int mm = (m < mrem) ? m : 0;
            const float* src = x + (size_t)(nb + mm) * K + k0 + kc * 4;
            cp_async16(dst, src, (m < mrem) ? 16 : 0);
        }
        for (int idx = tid; idx < BK * NC / 4; idx += NTH) {
            int kr = idx / (NC / 4);
            int j = (idx % (NC / 4)) * 4;
            const float* src = (j < F) ? (wl + (size_t)(kr + k0) * F + j)
                                       : (wr + (size_t)(kr + k0) * F + (j - F));
            uint32_t dst = (uint32_t)__cvta_generic_to_shared(&sBb[kr * NC + j]);
            cp_async16(dst, src, 16);
        }
    };

    load_tile(0, 0);
    cp_commit();

    constexpr int CG = NC / 8;
    const int tj = tid % CG;
    const int ti = tid / CG;
    const int m0 = ti * TM;
    const int jA = tj * 4;
    const int jB = jA + F;

    unsigned long long acc[TM][4];
#pragma unroll
    for (int i = 0; i < TM; ++i)
#pragma unroll
        for (int t = 0; t < 4; ++t) acc[i][t] = 0ull;

    for (int kb = 0; kb < KT; ++kb) {
        if (kb + 1 < KT) {
            load_tile(kb + 1, (kb + 1) & 1);
            cp_commit();
            cp_wait<1>();
        } else {
            cp_wait<0>();
        }
        __syncthreads();

        const float* bx = sX + (kb & 1) * BM * XS;
        const float* bb = sB + (kb & 1) * BK * NC;
#pragma unroll
        for (int k = 0; k < BK; ++k) {
            ulonglong2 bp0 = *reinterpret_cast<const ulonglong2*>(&bb[k * NC + jA]);
            ulonglong2 bp1 = *reinterpret_cast<const ulonglong2*>(&bb[k * NC + jB]);
#pragma unroll
            for (int i = 0; i < TM; ++i) {
                unsigned long long a2 = dup_f32(bx[(m0 + i) * XS + k]);
                fma_x2(acc[i][0], a2, bp0.x);
                fma_x2(acc[i][1], a2, bp0.y);
                fma_x2(acc[i][2], a2, bp1.x);
                fma_x2(acc[i][3], a2, bp1.y);
            }
        }
        __syncthreads();
    }

#pragma unroll
    for (int i = 0; i < TM; ++i) {
        int node = nb + m0 + i;
        if (node < n) {
            ulonglong2 v0, v1;
            v0.x = acc[i][0]; v0.y = acc[i][1];
            v1.x = acc[i][2]; v1.y = acc[i][3];
            *reinterpret_cast<ulonglong2*>(&ylr[(size_t)node * NC + jA]) = v0;
            *reinterpret_cast<ulonglong2*>(&ylr[(size_t)node * NC + jB]) = v1;
        }
    }
}

// ---------------------------------------------------------------------------
// per-node projection for small layers (K, F small): one thread per node
// ---------------------------------------------------------------------------
template <int K, int F>
__global__ void proj_pernode(const float* __restrict__ x, const float* __restrict__ wl,
                             const float* __restrict__ wr, float* __restrict__ ylr, int n) {
    constexpr int NC = 2 * F;
    __shared__ float sB[K * NC];
    for (int i = threadIdx.x; i < K * NC; i += blockDim.x) {
        int k = i / NC, j = i % NC;
        sB[i] = (j < F) ? wl[k * F + j] : wr[k * F + (j - F)];
    }
    __syncthreads();

    int node = blockIdx.x * blockDim.x + threadIdx.x;
    if (node >= n) return;

    float xv[K];
    const float4* xr = reinterpret_cast<const float4*>(x + (size_t)node * K);
#pragma unroll
    for (int c = 0; c < K / 4; ++c) {
        float4 v = xr[c];
        xv[c * 4 + 0] = v.x; xv[c * 4 + 1] = v.y; xv[c * 4 + 2] = v.z; xv[c * 4 + 3] = v.w;
    }
    float acc[NC];
#pragma unroll
    for (int j = 0; j < NC; ++j) acc[j] = 0.f;
#pragma unroll
    for (int k = 0; k < K; ++k) {
        float a = xv[k];
#pragma unroll
        for (int j = 0; j < NC; ++j) acc[j] = fmaf(a, sB[k * NC + j], acc[j]);
    }
    float4* o = reinterpret_cast<float4*>(ylr + (size_t)node * NC);
#pragma unroll
    for (int c = 0; c < NC / 4; ++c)
        o[c] = make_float4(acc[c * 4], acc[c * 4 + 1], acc[c * 4 + 2], acc[c * 4 + 3]);
}

// layer 3 projection: K=16 -> 9+9, padded layout: node stride 32 floats,
// yl at [0,9) (zeros to 16), yr at [16,25)
__global__ void proj3_pernode(const float* __restrict__ x, const float* __restrict__ wl,
                              const float* __restrict__ wr, float* __restrict__ ylr3, int n) {
    __shared__ float swl[16 * 9];
    __shared__ float swr[16 * 9];
    for (int i = threadIdx.x; i < 144; i += blockDim.x) {
        swl[i] = wl[i];
        swr[i] = wr[i];
    }
    __syncthreads();

    int node = blockIdx.x * blockDim.x + threadIdx.x;
    if (node >= n) return;

    float xv[16];
    const float4* xr = reinterpret_cast<const float4*>(x + (size_t)node * 16);
#pragma unroll
    for (int c = 0; c < 4; ++c) {
        float4 v = xr[c];
        xv[c * 4 + 0] = v.x; xv[c * 4 + 1] = v.y; xv[c * 4 + 2] = v.z; xv[c * 4 + 3] = v.w;
    }
    float al[9], ar[9];
#pragma unroll
    for (int j = 0; j < 9; ++j) { al[j] = 0.f; ar[j] = 0.f; }
#pragma unroll
    for (int k = 0; k < 16; ++k) {
        float a = xv[k];
#pragma unroll
        for (int j = 0; j < 9; ++j) {
            al[j] = fmaf(a, swl[k * 9 + j], al[j]);
            ar[j] = fmaf(a, swr[k * 9 + j], ar[j]);
        }
    }
    float4* o = reinterpret_cast<float4*>(ylr3 + (size_t)node * 32);
    o[0] = make_float4(al[0], al[1], al[2], al[3]);
    o[1] = make_float4(al[4], al[5], al[6], al[7]);
    o[2] = make_float4(al[8], 0.f, 0.f, 0.f);
    o[3] = make_float4(0.f, 0.f, 0.f, 0.f);
    o[4] = make_float4(ar[0], ar[1], ar[2], ar[3]);
    o[5] = make_float4(ar[4], ar[5], ar[6], ar[7]);
    ylr3[(size_t)node * 32 + 24] = ar[8];
}

// ---------------------------------------------------------------------------
// gather + combine (fused): warp per node.
// out[i] = [relu]( mean_{j in N(i)} yl[j] + yr[i] + b )
// Lanes split: CH = F/4 float4 chunks, 32/CH edges processed per iteration.
// ---------------------------------------------------------------------------
template <int F, bool RELU>
__global__ void gather_combine(const float* __restrict__ ylr, const int* __restrict__ esrc,
                               const int* __restrict__ off, const int* __restrict__ cnt,
                               const float* __restrict__ bias, float* __restrict__ out, int n) {
    constexpr int CH = F / 4;
    constexpr int EPW = 32 / CH;
    int w = (blockIdx.x * blockDim.x + threadIdx.x) >> 5;
    if (w >= n) return;
    int lane = threadIdx.x & 31;
    int c = lane % CH, g = lane / CH;
    int start = off[w], deg = cnt[w];

    float4 acc = make_float4(0.f, 0.f, 0.f, 0.f);
    const float4* y4 = reinterpret_cast<const float4*>(ylr);
    for (int j = g; j < deg; j += EPW) {
        int s = __ldg(esrc + start + j);
        float4 v = y4[(size_t)s * (F / 2) + c];
        acc.x += v.x; acc.y += v.y; acc.z += v.z; acc.w += v.w;
    }
#pragma unroll
    for (int st = 16; st >= CH; st >>= 1) {
        acc.x += __shfl_xor_sync(0xFFFFFFFFu, acc.x, st);
        acc.y += __shfl_xor_sync(0xFFFFFFFFu, acc.y, st);
        acc.z += __shfl_xor_sync(0xFFFFFFFFu, acc.z, st);
        acc.w += __shfl_xor_sync(0xFFFFFFFFu, acc.w, st);
    }
    if (lane < CH) {
        float iv = __frcp_rn(fmaxf((float)deg, 1.0f));
        float4 r = y4[(size_t)w * (F / 2) + (F / 4) + c];
        float4 b = reinterpret_cast<const float4*>(bias)[c];
        float4 v;
        v.x = fmaf(acc.x, iv, r.x) + b.x;
        v.y = fmaf(acc.y, iv, r.y) + b.y;
        v.z = fmaf(acc.z, iv, r.z) + b.z;
        v.w = fmaf(acc.w, iv, r.w) + b.w;
        if (RELU) {
            v.x = fmaxf(v.x, 0.f); v.y = fmaxf(v.y, 0.f);
            v.z = fmaxf(v.z, 0.f); v.w = fmaxf(v.w, 0.f);
        }
        reinterpret_cast<float4*>(out)[(size_t)w * CH + c] = v;
    }
}

// final layer gather: padded yl (16-wide, stride 32), 9 outputs, no relu
__global__ void gather9(const float* __restrict__ ylr3, const int* __restrict__ esrc,
                        const int* __restrict__ off, const int* __restrict__ cnt,
                        const float* __restrict__ bias, float* __restrict__ out, int n) {
    int w = (blockIdx.x * blockDim.x + threadIdx.x) >> 5;
    if (w >= n) return;
    int lane = threadIdx.x & 31;
    int c = lane % 4, g = lane / 4;  // 8 edges per iter
    int start = off[w], deg = cnt[w];

    float4 acc = make_float4(0.f, 0.f, 0.f, 0.f);
    const float4* y4 = reinterpret_cast<const float4*>(ylr3);
    for (int j = g; j < deg; j += 8) {
        int s = __ldg(esrc + start + j);
        float4 v = y4[(size_t)s * 8 + c];
        acc.x += v.x; acc.y += v.y; acc.z += v.z; acc.w += v.w;
    }
#pragma unroll
    for (int st = 16; st >= 4; st >>= 1) {
        acc.x += __shfl_xor_sync(0xFFFFFFFFu, acc.x, st);
        acc.y += __shfl_xor_sync(0xFFFFFFFFu, acc.y, st);
        acc.z += __shfl_xor_sync(0xFFFFFFFFu, acc.z, st);
        acc.w += __shfl_xor_sync(0xFFFFFFFFu, acc.w, st);
    }
    if (lane < 4) {
        float iv = __frcp_rn(fmaxf((float)deg, 1.0f));
        float a[4] = {acc.x, acc.y, acc.z, acc.w};
#pragma unroll
        for (int t = 0; t < 4; ++t) {
            int j = c * 4 + t;
            if (j < 9) {
                float yr = ylr3[(size_t)w * 32 + 16 + j];
                out[(size_t)w * 9 + j] = fmaf(a[t], iv, yr + __ldg(bias + j));
            }
        }
    }
}

// ---------------------------------------------------------------------------
// launch
// ---------------------------------------------------------------------------
extern "C" void kernel_launch(void* const* d_in, const int* in_sizes, int n_in,
                              void* d_out, int out_size) {
    const float* emb = (const float*)d_in[0];
    const int* ei = (const int*)d_in[1];
    // d_in[2] = edge_attr, unused by SAGEConv
    const float* wl0 = (const float*)d_in[3];
    const float* wr0 = (const float*)d_in[4];
    const float* b0  = (const float*)d_in[5];
    const float* wl1 = (const float*)d_in[6];
    const float* wr1 = (const float*)d_in[7];
    const float* b1  = (const float*)d_in[8];
    const float* wl2 = (const float*)d_in[9];
    const float* wr2 = (const float*)d_in[10];
    const float* b2  = (const float*)d_in[11];
    const float* wl3 = (const float*)d_in[12];
    const float* wr3 = (const float*)d_in[13];
    const float* b3  = (const float*)d_in[14];
    float* out = (float*)d_out;

    const int n = in_sizes[0] / 128;
    const int E = in_sizes[1] / 2;
    const int* src = ei;
    const int* dst = ei + E;

    float *ylr, *xbuf;
    int *cnt, *off, *cur, *esrc, *bsum;
    cudaGetSymbolAddress((void**)&ylr, g_ylr);
    cudaGetSymbolAddress((void**)&xbuf, g_x);
    cudaGetSymbolAddress((void**)&cnt, g_cnt);
    cudaGetSymbolAddress((void**)&off, g_off);
    cudaGetSymbolAddress((void**)&cur, g_cur);
    cudaGetSymbolAddress((void**)&esrc, g_esrc);
    cudaGetSymbolAddress((void**)&bsum, g_bsum);

    auto cdiv = [](int a, int b) { return (a + b - 1) / b; };
    const int TB = 256;
    const int nb = cdiv(n, 512);

    const int SM0 = (2 * 128 * 36 + 2 * 32 * 128) * 4;  // 69632
    const int SM1 = (2 * 128 * 36 + 2 * 32 * 64) * 4;   // 53248
    cudaFuncSetAttribute((const void*)sgemm_proj_x2<128, 128, 128, 32>,
                         cudaFuncAttributeMaxDynamicSharedMemorySize, SM0);
    cudaFuncSetAttribute((const void*)sgemm_proj_x2<64, 64, 128, 32>,
                         cudaFuncAttributeMaxDynamicSharedMemorySize, SM1);

    // ---- CSR build (once; reused by all 4 layers) ----
    zero_int<<<cdiv(n, TB), TB>>>(cnt, n);
    hist_kernel<<<cdiv(E, TB), TB>>>(dst, cnt, E);
    scan_block<<<nb, 512>>>(cnt, off, bsum, n);
    scan_sums<<<1, 512>>>(bsum, nb);
    scan_add<<<nb, 512>>>(off, bsum, cur, n);
    fill_kernel<<<cdiv(E, TB), TB>>>(src, dst, cur, esrc, E);

    // ---- layer 0: 128 -> 64, relu ----
    sgemm_proj_x2<128, 128, 128, 32><<<cdiv(n, 128), 256, SM0>>>(emb, wl0, wr0, ylr, n);
    gather_combine<64, true><<<cdiv(n * 32, TB), TB>>>(ylr, esrc, off, cnt, b0, xbuf, n);

    // ---- layer 1: 64 -> 32, relu ----
    sgemm_proj_x2<64, 64, 128, 32><<<cdiv(n, 128), 128, SM1>>>(xbuf, wl1, wr1, ylr, n);
    gather_combine<32, true><<<cdiv(n * 32, TB), TB>>>(ylr, esrc, off, cnt, b1, xbuf, n);

    // ---- layer 2: 32 -> 16, relu ----
    proj_pernode<32, 16><<<cdiv(n, TB), TB>>>(xbuf, wl2, wr2, ylr, n);
    gather_combine<16, true><<<cdiv(n * 32, TB), TB>>>(ylr, esrc, off, cnt, b2, xbuf, n);

    // ---- layer 3: 16 -> 9, no relu, write d_out ----
    proj3_pernode<<<cdiv(n, TB), TB>>>(xbuf, wl3, wr3, ylr, n);
    gather9<<<cdiv(n * 32, TB), TB>>>(ylr, esrc, off, cnt, b3, out, n);
}

// round 5
// speedup vs baseline: 1.1782x; 1.0207x over previous
#include <cuda_runtime.h>
#include <cstdint>

#define NMAX 100000
#define EMAX 600000

// Scratch (static device globals — allocation-free per harness rules)
__device__ __align__(16) float g_ylr[NMAX * 128];  // projected [y_l | y_r]
__device__ __align__(16) float g_x[NMAX * 64];     // layer activations
__device__ int g_cnt[NMAX];    // in-degree
__device__ int g_off[NMAX];    // CSR offsets (exclusive scan of cnt)
__device__ int g_cur[NMAX];    // fill cursors
__device__ int g_esrc[EMAX];   // src node per edge, sorted by dst
__device__ int g_bsum[512];    // scan block sums

// ---------------------------------------------------------------------------
// cp.async + packed fma helpers
// ---------------------------------------------------------------------------
__device__ __forceinline__ void cp_async16(uint32_t dst, const void* src, int src_bytes) {
    asm volatile("cp.async.cg.shared.global [%0], [%1], 16, %2;\n"
                 :: "r"(dst), "l"(src), "r"(src_bytes));
}
__device__ __forceinline__ void cp_commit() { asm volatile("cp.async.commit_group;\n"); }
template <int N>
__device__ __forceinline__ void cp_wait() { asm volatile("cp.async.wait_group %0;\n" :: "n"(N)); }

__device__ __forceinline__ void fma_x2(unsigned long long& acc, unsigned long long a2,
                                       unsigned long long b2) {
    asm("fma.rn.f32x2 %0, %1, %2, %0;" : "+l"(acc) : "l"(a2), "l"(b2));
}
__device__ __forceinline__ unsigned long long dup_f32(float a) {
    unsigned long long r;
    asm("mov.b64 %0, {%1, %1};" : "=l"(r) : "f"(a));
    return r;
}

// ---------------------------------------------------------------------------
// CSR build: hist -> block scan -> sums scan -> add+cursor -> fill
// ---------------------------------------------------------------------------
__global__ void zero_int(int* __restrict__ p, int n) {
    int i = blockIdx.x * blockDim.x + threadIdx.x;
    if (i < n) p[i] = 0;
}

__global__ void hist_kernel(const int* __restrict__ dst, int* __restrict__ cnt, int E) {
    int i = blockIdx.x * blockDim.x + threadIdx.x;
    if (i < E) atomicAdd(&cnt[dst[i]], 1);
}

// shuffle-based inclusive scan of a 512-wide block; outputs exclusive
__device__ __forceinline__ int block_exscan_512(int v, int tid, int* warp_sums /*smem[16]*/,
                                                int* total) {
    int lane = tid & 31, wid = tid >> 5;
    int inc = v;
#pragma unroll
    for (int st = 1; st < 32; st <<= 1) {
        int t = __shfl_up_sync(0xFFFFFFFFu, inc, st);
        if (lane >= st) inc += t;
    }
    if (lane == 31) warp_sums[wid] = inc;
    __syncthreads();
    if (wid == 0) {
        int ws = (lane < 16) ? warp_sums[lane] : 0;
#pragma unroll
        for (int st = 1; st < 16; st <<= 1) {
            int t = __shfl_up_sync(0xFFFFFFFFu, ws, st);
            if (lane >= st) ws += t;
        }
        if (lane < 16) warp_sums[lane] = ws;
    }
    __syncthreads();
    int base = (wid > 0) ? warp_sums[wid - 1] : 0;
    if (total) *total = warp_sums[15];
    return base + inc - v;  // exclusive
}

__global__ void scan_block(const int* __restrict__ cnt, int* __restrict__ off,
                           int* __restrict__ bsum, int n) {
    __shared__ int ws[16];
    int i = blockIdx.x * 512 + threadIdx.x;
    int v = (i < n) ? cnt[i] : 0;
    int total;
    int ex = block_exscan_512(v, threadIdx.x, ws, &total);
    if (i < n) off[i] = ex;
    if (threadIdx.x == 0) bsum[blockIdx.x] = total;
}

__global__ void scan_sums(int* __restrict__ bsum, int nb) {
    __shared__ int ws[16];
    int v = (threadIdx.x < nb) ? bsum[threadIdx.x] : 0;
    int ex = block_exscan_512(v, threadIdx.x, ws, nullptr);
    if (threadIdx.x < nb) bsum[threadIdx.x] = ex;
}

__global__ void scan_add(int* __restrict__ off, const int* __restrict__ bsum,
                         int* __restrict__ cur, int n) {
    int i = blockIdx.x * 512 + threadIdx.x;
    if (i < n) {
        int o = off[i] + bsum[blockIdx.x];
        off[i] = o;
        cur[i] = o;
    }
}

__global__ void fill_kernel(const int* __restrict__ src, const int* __restrict__ dst,
                            int* __restrict__ cur, int* __restrict__ esrc, int E) {
    int e = blockIdx.x * blockDim.x + threadIdx.x;
    if (e < E) {
        int p = atomicAdd(&cur[dst[e]], 1);
        esrc[p] = src[e];
    }
}

// ---------------------------------------------------------------------------
// projection GEMM (packed f32x2): ylr[n x NC] = x[n x K] @ [wl | wr]
// ---------------------------------------------------------------------------
template <int K, int NC, int BM, int BK, int MINBLK>
__global__ void __launch_bounds__((BM / 8) * (NC / 8), MINBLK)
sgemm_proj_x2(const float* __restrict__ x, const float* __restrict__ wl,
              const float* __restrict__ wr, float* __restrict__ ylr, int n) {
    constexpr int TM = 8;
    constexpr int PAD = 4;
    constexpr int F = NC / 2;
    constexpr int NTH = (BM / TM) * (NC / 8);
    constexpr int KT = K / BK;
    constexpr int XS = BK + PAD;

    extern __shared__ float sm[];
    float* sX = sm;                    // [2][BM * XS]
    float* sB = sm + 2 * BM * XS;      // [2][BK * NC]

    const int tid = threadIdx.x;
    const int nb = blockIdx.x * BM;
    const int mrem = n - nb;

    auto load_tile = [&](int kb, int buf) {
        const int k0 = kb * BK;
        float* sXb = sX + buf * BM * XS;
        float* sBb = sB + buf * BK * NC;
        for (int idx = tid; idx < BM * BK / 4; idx += NTH) {
            int m = idx / (BK / 4);
            int kc = idx % (BK / 4);
            uint32_t dst = (uint32_t)__cvta_generic_to_shared(&sXb[m * XS + kc * 4]);
            int mm = (m < mrem) ? m : 0;
            const float* src = x + (size_t)(nb + mm) * K + k0 + kc * 4;
            cp_async16(dst, src, (m < mrem) ? 16 : 0);
        }
        for (int idx = tid; idx < BK * NC / 4; idx += NTH) {
            int kr = idx / (NC / 4);
            int j = (idx % (NC / 4)) * 4;
            const float* src = (j < F) ? (wl + (size_t)(kr + k0) * F + j)
                                       : (wr + (size_t)(kr + k0) * F + (j - F));
            uint32_t dst = (uint32_t)__cvta_generic_to_shared(&sBb[kr * NC + j]);
            cp_async16(dst, src, 16);
        }
    };

    load_tile(0, 0);
    cp_commit();

    constexpr int CG = NC / 8;
    const int tj = tid % CG;
    const int ti = tid / CG;
    const int m0 = ti * TM;
    const int jA = tj * 4;
    const int jB = jA + F;

    unsigned long long acc[TM][4];
#pragma unroll
    for (int i = 0; i < TM; ++i)
#pragma unroll
        for (int t = 0; t < 4; ++t) acc[i][t] = 0ull;

    for (int kb = 0; kb < KT; ++kb) {
        if (kb + 1 < KT) {
            load_tile(kb + 1, (kb + 1) & 1);
            cp_commit();
            cp_wait<1>();
        } else {
            cp_wait<0>();
        }
        __syncthreads();

        const float* bx = sX + (kb & 1) * BM * XS;
        const float* bb = sB + (kb & 1) * BK * NC;
#pragma unroll
        for (int k = 0; k < BK; ++k) {
            ulonglong2 bp0 = *reinterpret_cast<const ulonglong2*>(&bb[k * NC + jA]);
            ulonglong2 bp1 = *reinterpret_cast<const ulonglong2*>(&bb[k * NC + jB]);
#pragma unroll
            for (int i = 0; i < TM; ++i) {
                unsigned long long a2 = dup_f32(bx[(m0 + i) * XS + k]);
                fma_x2(acc[i][0], a2, bp0.x);
                fma_x2(acc[i][1], a2, bp0.y);
                fma_x2(acc[i][2], a2, bp1.x);
                fma_x2(acc[i][3], a2, bp1.y);
            }
        }
        __syncthreads();
    }

#pragma unroll
    for (int i = 0; i < TM; ++i) {
        int node = nb + m0 + i;
        if (node < n) {
            ulonglong2 v0, v1;
            v0.x = acc[i][0]; v0.y = acc[i][1];
            v1.x = acc[i][2]; v1.y = acc[i][3];
            *reinterpret_cast<ulonglong2*>(&ylr[(size_t)node * NC + jA]) = v0;
            *reinterpret_cast<ulonglong2*>(&ylr[(size_t)node * NC + jB]) = v1;
        }
    }
}

// ---------------------------------------------------------------------------
// per-node projection for small layers (K, F small): one thread per node
// ---------------------------------------------------------------------------
template <int K, int F>
__global__ void proj_pernode(const float* __restrict__ x, const float* __restrict__ wl,
                             const float* __restrict__ wr, float* __restrict__ ylr, int n) {
    constexpr int NC = 2 * F;
    __shared__ float sB[K * NC];
    for (int i = threadIdx.x; i < K * NC; i += blockDim.x) {
        int k = i / NC, j = i % NC;
        sB[i] = (j < F) ? wl[k * F + j] : wr[k * F + (j - F)];
    }
    __syncthreads();

    int node = blockIdx.x * blockDim.x + threadIdx.x;
    if (node >= n) return;

    float xv[K];
    const float4* xr = reinterpret_cast<const float4*>(x + (size_t)node * K);
#pragma unroll
    for (int c = 0; c < K / 4; ++c) {
        float4 v = xr[c];
        xv[c * 4 + 0] = v.x; xv[c * 4 + 1] = v.y; xv[c * 4 + 2] = v.z; xv[c * 4 + 3] = v.w;
    }
    float acc[NC];
#pragma unroll
    for (int j = 0; j < NC; ++j) acc[j] = 0.f;
#pragma unroll
    for (int k = 0; k < K; ++k) {
        float a = xv[k];
#pragma unroll
        for (int j = 0; j < NC; ++j) acc[j] = fmaf(a, sB[k * NC + j], acc[j]);
    }
    float4* o = reinterpret_cast<float4*>(ylr + (size_t)node * NC);
#pragma unroll
    for (int c = 0; c < NC / 4; ++c)
        o[c] = make_float4(acc[c * 4], acc[c * 4 + 1], acc[c * 4 + 2], acc[c * 4 + 3]);
}

// layer 3 projection: K=16 -> 9+9, padded layout: node stride 32 floats,
// yl at [0,9) (zeros to 16), yr at [16,25)
__global__ void proj3_pernode(const float* __restrict__ x, const float* __restrict__ wl,
                              const float* __restrict__ wr, float* __restrict__ ylr3, int n) {
    __shared__ float swl[16 * 9];
    __shared__ float swr[16 * 9];
    for (int i = threadIdx.x; i < 144; i += blockDim.x) {
        swl[i] = wl[i];
        swr[i] = wr[i];
    }
    __syncthreads();

    int node = blockIdx.x * blockDim.x + threadIdx.x;
    if (node >= n) return;

    float xv[16];
    const float4* xr = reinterpret_cast<const float4*>(x + (size_t)node * 16);
#pragma unroll
    for (int c = 0; c < 4; ++c) {
        float4 v = xr[c];
        xv[c * 4 + 0] = v.x; xv[c * 4 + 1] = v.y; xv[c * 4 + 2] = v.z; xv[c * 4 + 3] = v.w;
    }
    float al[9], ar[9];
#pragma unroll
    for (int j = 0; j < 9; ++j) { al[j] = 0.f; ar[j] = 0.f; }
#pragma unroll
    for (int k = 0; k < 16; ++k) {
        float a = xv[k];
#pragma unroll
        for (int j = 0; j < 9; ++j) {
            al[j] = fmaf(a, swl[k * 9 + j], al[j]);
            ar[j] = fmaf(a, swr[k * 9 + j], ar[j]);
        }
    }
    float4* o = reinterpret_cast<float4*>(ylr3 + (size_t)node * 32);
    o[0] = make_float4(al[0], al[1], al[2], al[3]);
    o[1] = make_float4(al[4], al[5], al[6], al[7]);
    o[2] = make_float4(al[8], 0.f, 0.f, 0.f);
    o[3] = make_float4(0.f, 0.f, 0.f, 0.f);
    o[4] = make_float4(ar[0], ar[1], ar[2], ar[3]);
    o[5] = make_float4(ar[4], ar[5], ar[6], ar[7]);
    ylr3[(size_t)node * 32 + 24] = ar[8];
}

// ---------------------------------------------------------------------------
// gather + combine (fused): warp per node.
// ---------------------------------------------------------------------------
template <int F, bool RELU>
__global__ void gather_combine(const float* __restrict__ ylr, const int* __restrict__ esrc,
                               const int* __restrict__ off, const int* __restrict__ cnt,
                               const float* __restrict__ bias, float* __restrict__ out, int n) {
    constexpr int CH = F / 4;
    constexpr int EPW = 32 / CH;
    int w = (blockIdx.x * blockDim.x + threadIdx.x) >> 5;
    if (w >= n) return;
    int lane = threadIdx.x & 31;
    int c = lane % CH, g = lane / CH;
    int start = off[w], deg = cnt[w];

    float4 acc = make_float4(0.f, 0.f, 0.f, 0.f);
    const float4* y4 = reinterpret_cast<const float4*>(ylr);
    for (int j = g; j < deg; j += EPW) {
        int s = __ldg(esrc + start + j);
        float4 v = y4[(size_t)s * (F / 2) + c];
        acc.x += v.x; acc.y += v.y; acc.z += v.z; acc.w += v.w;
    }
#pragma unroll
    for (int st = 16; st >= CH; st >>= 1) {
        acc.x += __shfl_xor_sync(0xFFFFFFFFu, acc.x, st);
        acc.y += __shfl_xor_sync(0xFFFFFFFFu, acc.y, st);
        acc.z += __shfl_xor_sync(0xFFFFFFFFu, acc.z, st);
        acc.w += __shfl_xor_sync(0xFFFFFFFFu, acc.w, st);
    }
    if (lane < CH) {
        float iv = __frcp_rn(fmaxf((float)deg, 1.0f));
        float4 r = y4[(size_t)w * (F / 2) + (F / 4) + c];
        float4 b = reinterpret_cast<const float4*>(bias)[c];
        float4 v;
        v.x = fmaf(acc.x, iv, r.x) + b.x;
        v.y = fmaf(acc.y, iv, r.y) + b.y;
        v.z = fmaf(acc.z, iv, r.z) + b.z;
        v.w = fmaf(acc.w, iv, r.w) + b.w;
        if (RELU) {
            v.x = fmaxf(v.x, 0.f); v.y = fmaxf(v.y, 0.f);
            v.z = fmaxf(v.z, 0.f); v.w = fmaxf(v.w, 0.f);
        }
        reinterpret_cast<float4*>(out)[(size_t)w * CH + c] = v;
    }
}

// final layer gather: padded yl (16-wide, stride 32), 9 outputs, no relu
__global__ void gather9(const float* __restrict__ ylr3, const int* __restrict__ esrc,
                        const int* __restrict__ off, const int* __restrict__ cnt,
                        const float* __restrict__ bias, float* __restrict__ out, int n) {
    int w = (blockIdx.x * blockDim.x + threadIdx.x) >> 5;
    if (w >= n) return;
    int lane = threadIdx.x & 31;
    int c = lane % 4, g = lane / 4;  // 8 edges per iter
    int start = off[w], deg = cnt[w];

    float4 acc = make_float4(0.f, 0.f, 0.f, 0.f);
    const float4* y4 = reinterpret_cast<const float4*>(ylr3);
    for (int j = g; j < deg; j += 8) {
        int s = __ldg(esrc + start + j);
        float4 v = y4[(size_t)s * 8 + c];
        acc.x += v.x; acc.y += v.y; acc.z += v.z; acc.w += v.w;
    }
#pragma unroll
    for (int st = 16; st >= 4; st >>= 1) {
        acc.x += __shfl_xor_sync(0xFFFFFFFFu, acc.x, st);
        acc.y += __shfl_xor_sync(0xFFFFFFFFu, acc.y, st);
        acc.z += __shfl_xor_sync(0xFFFFFFFFu, acc.z, st);
        acc.w += __shfl_xor_sync(0xFFFFFFFFu, acc.w, st);
    }
    if (lane < 4) {
        float iv = __frcp_rn(fmaxf((float)deg, 1.0f));
        float a[4] = {acc.x, acc.y, acc.z, acc.w};
#pragma unroll
        for (int t = 0; t < 4; ++t) {
            int j = c * 4 + t;
            if (j < 9) {
                float yr = ylr3[(size_t)w * 32 + 16 + j];
                out[(size_t)w * 9 + j] = fmaf(a[t], iv, yr + __ldg(bias + j));
            }
        }
    }
}

// ---------------------------------------------------------------------------
// launch
// ---------------------------------------------------------------------------
extern "C" void kernel_launch(void* const* d_in, const int* in_sizes, int n_in,
                              void* d_out, int out_size) {
    const float* emb = (const float*)d_in[0];
    const int* ei = (const int*)d_in[1];
    // d_in[2] = edge_attr, unused by SAGEConv
    const float* wl0 = (const float*)d_in[3];
    const float* wr0 = (const float*)d_in[4];
    const float* b0  = (const float*)d_in[5];
    const float* wl1 = (const float*)d_in[6];
    const float* wr1 = (const float*)d_in[7];
    const float* b1  = (const float*)d_in[8];
    const float* wl2 = (const float*)d_in[9];
    const float* wr2 = (const float*)d_in[10];
    const float* b2  = (const float*)d_in[11];
    const float* wl3 = (const float*)d_in[12];
    const float* wr3 = (const float*)d_in[13];
    const float* b3  = (const float*)d_in[14];
    float* out = (float*)d_out;

    const int n = in_sizes[0] / 128;
    const int E = in_sizes[1] / 2;
    const int* src = ei;
    const int* dst = ei + E;

    float *ylr, *xbuf;
    int *cnt, *off, *cur, *esrc, *bsum;
    cudaGetSymbolAddress((void**)&ylr, g_ylr);
    cudaGetSymbolAddress((void**)&xbuf, g_x);
    cudaGetSymbolAddress((void**)&cnt, g_cnt);
    cudaGetSymbolAddress((void**)&off, g_off);
    cudaGetSymbolAddress((void**)&cur, g_cur);
    cudaGetSymbolAddress((void**)&esrc, g_esrc);
    cudaGetSymbolAddress((void**)&bsum, g_bsum);

    auto cdiv = [](int a, int b) { return (a + b - 1) / b; };
    const int TB = 256;
    const int nb = cdiv(n, 512);

    // layer0: BM=64 => smem 51200B, 128 threads, 4 blocks/SM
    const int SM0 = (2 * 64 * 36 + 2 * 32 * 128) * 4;   // 51200
    const int SM1 = (2 * 128 * 36 + 2 * 32 * 64) * 4;   // 53248
    cudaFuncSetAttribute((const void*)sgemm_proj_x2<128, 128, 64, 32, 4>,
                         cudaFuncAttributeMaxDynamicSharedMemorySize, SM0);
    cudaFuncSetAttribute((const void*)sgemm_proj_x2<64, 64, 128, 32, 4>,
                         cudaFuncAttributeMaxDynamicSharedMemorySize, SM1);

    // ---- CSR build (once; reused by all 4 layers) ----
    zero_int<<<cdiv(n, TB), TB>>>(cnt, n);
    hist_kernel<<<cdiv(E, TB), TB>>>(dst, cnt, E);
    scan_block<<<nb, 512>>>(cnt, off, bsum, n);
    scan_sums<<<1, 512>>>(bsum, nb);
    scan_add<<<nb, 512>>>(off, bsum, cur, n);
    fill_kernel<<<cdiv(E, TB), TB>>>(src, dst, cur, esrc, E);

    // ---- layer 0: 128 -> 64, relu ----
    sgemm_proj_x2<128, 128, 64, 32, 4><<<cdiv(n, 64), 128, SM0>>>(emb, wl0, wr0, ylr, n);
    gather_combine<64, true><<<cdiv(n * 32, TB), TB>>>(ylr, esrc, off, cnt, b0, xbuf, n);

    // ---- layer 1: 64 -> 32, relu ----
    sgemm_proj_x2<64, 64, 128, 32, 4><<<cdiv(n, 128), 128, SM1>>>(xbuf, wl1, wr1, ylr, n);
    gather_combine<32, true><<<cdiv(n * 32, TB), TB>>>(ylr, esrc, off, cnt, b1, xbuf, n);

    // ---- layer 2: 32 -> 16, relu ----
    proj_pernode<32, 16><<<cdiv(n, TB), TB>>>(xbuf, wl2, wr2, ylr, n);
    gather_combine<16, true><<<cdiv(n * 32, TB), TB>>>(ylr, esrc, off, cnt, b2, xbuf, n);

    // ---- layer 3: 16 -> 9, no relu, write d_out ----
    proj3_pernode<<<cdiv(n, TB), TB>>>(xbuf, wl3, wr3, ylr, n);
    gather9<<<cdiv(n * 32, TB), TB>>>(ylr, esrc, off, cnt, b3, out, n);
}

// round 6
// speedup vs baseline: 1.2206x; 1.0360x over previous
#include <cuda_runtime.h>
#include <cstdint>

#define NMAX 100000
#define EMAX 600000

// Scratch (static device globals — allocation-free per harness rules)
__device__ __align__(16) float g_ylr[NMAX * 128];  // projected [y_l | y_r]
__device__ __align__(16) float g_x[NMAX * 64];     // layer activations
__device__ int g_cnt[NMAX];    // in-degree
__device__ int g_off[NMAX];    // CSR offsets (exclusive scan of cnt)
__device__ int g_cur[NMAX];    // fill cursors
__device__ int g_esrc[EMAX];   // src node per edge, sorted by dst
__device__ int g_bsum[512];    // scan block sums

// ---------------------------------------------------------------------------
// cp.async + packed fma helpers
// ---------------------------------------------------------------------------
__device__ __forceinline__ void cp_async16(uint32_t dst, const void* src, int src_bytes) {
    asm volatile("cp.async.cg.shared.global [%0], [%1], 16, %2;\n"
                 :: "r"(dst), "l"(src), "r"(src_bytes));
}
__device__ __forceinline__ void cp_commit() { asm volatile("cp.async.commit_group;\n"); }
template <int N>
__device__ __forceinline__ void cp_wait() { asm volatile("cp.async.wait_group %0;\n" :: "n"(N)); }

__device__ __forceinline__ void fma_x2(unsigned long long& acc, unsigned long long a2,
                                       unsigned long long b2) {
    asm("fma.rn.f32x2 %0, %1, %2, %0;" : "+l"(acc) : "l"(a2), "l"(b2));
}
__device__ __forceinline__ unsigned long long dup_f32(float a) {
    unsigned long long r;
    asm("mov.b64 %0, {%1, %1};" : "=l"(r) : "f"(a));
    return r;
}

// ---------------------------------------------------------------------------
// CSR build: hist -> block scan -> sums scan -> add+cursor -> fill
// ---------------------------------------------------------------------------
__global__ void zero_int(int* __restrict__ p, int n) {
    int i = blockIdx.x * blockDim.x + threadIdx.x;
    if (i < n) p[i] = 0;
}

__global__ void hist_kernel(const int* __restrict__ dst, int* __restrict__ cnt, int E) {
    int i = blockIdx.x * blockDim.x + threadIdx.x;
    if (i < E) atomicAdd(&cnt[dst[i]], 1);
}

// shuffle-based exclusive scan of a 512-wide block
__device__ __forceinline__ int block_exscan_512(int v, int tid, int* warp_sums /*smem[16]*/,
                                                int* total) {
    int lane = tid & 31, wid = tid >> 5;
    int inc = v;
#pragma unroll
    for (int st = 1; st < 32; st <<= 1) {
        int t = __shfl_up_sync(0xFFFFFFFFu, inc, st);
        if (lane >= st) inc += t;
    }
    if (lane == 31) warp_sums[wid] = inc;
    __syncthreads();
    if (wid == 0) {
        int ws = (lane < 16) ? warp_sums[lane] : 0;
#pragma unroll
        for (int st = 1; st < 16; st <<= 1) {
            int t = __shfl_up_sync(0xFFFFFFFFu, ws, st);
            if (lane >= st) ws += t;
        }
        if (lane < 16) warp_sums[lane] = ws;
    }
    __syncthreads();
    int base = (wid > 0) ? warp_sums[wid - 1] : 0;
    if (total) *total = warp_sums[15];
    return base + inc - v;  // exclusive
}

__global__ void scan_block(const int* __restrict__ cnt, int* __restrict__ off,
                           int* __restrict__ bsum, int n) {
    __shared__ int ws[16];
    int i = blockIdx.x * 512 + threadIdx.x;
    int v = (i < n) ? cnt[i] : 0;
    int total;
    int ex = block_exscan_512(v, threadIdx.x, ws, &total);
    if (i < n) off[i] = ex;
    if (threadIdx.x == 0) bsum[blockIdx.x] = total;
}

__global__ void scan_sums(int* __restrict__ bsum, int nb) {
    __shared__ int ws[16];
    int v = (threadIdx.x < nb) ? bsum[threadIdx.x] : 0;
    int ex = block_exscan_512(v, threadIdx.x, ws, nullptr);
    if (threadIdx.x < nb) bsum[threadIdx.x] = ex;
}

__global__ void scan_add(int* __restrict__ off, const int* __restrict__ bsum,
                         int* __restrict__ cur, int n) {
    int i = blockIdx.x * 512 + threadIdx.x;
    if (i < n) {
        int o = off[i] + bsum[blockIdx.x];
        off[i] = o;
        cur[i] = o;
    }
}

__global__ void fill_kernel(const int* __restrict__ src, const int* __restrict__ dst,
                            int* __restrict__ cur, int* __restrict__ esrc, int E) {
    int e = blockIdx.x * blockDim.x + threadIdx.x;
    if (e < E) {
        int p = atomicAdd(&cur[dst[e]], 1);
        esrc[p] = src[e];
    }
}

// ---------------------------------------------------------------------------
// projection GEMM (packed f32x2): ylr[n x NC] = x[n x K] @ [wl | wr]
// ---------------------------------------------------------------------------
template <int K, int NC, int BM, int BK, int MINBLK>
__global__ void __launch_bounds__((BM / 8) * (NC / 8), MINBLK)
sgemm_proj_x2(const float* __restrict__ x, const float* __restrict__ wl,
              const float* __restrict__ wr, float* __restrict__ ylr, int n) {
    constexpr int TM = 8;
    constexpr int PAD = 4;
    constexpr int F = NC / 2;
    constexpr int NTH = (BM / TM) * (NC / 8);
    constexpr int KT = K / BK;
    constexpr int XS = BK + PAD;

    extern __shared__ float sm[];
    float* sX = sm;                    // [2][BM * XS]
    float* sB = sm + 2 * BM * XS;      // [2][BK * NC]

    const int tid = threadIdx.x;
    const int nb = blockIdx.x * BM;
    const int mrem = n - nb;

    auto load_tile = [&](int kb, int buf) {
        const int k0 = kb * BK;
        float* sXb = sX + buf * BM * XS;
        float* sBb = sB + buf * BK * NC;
        for (int idx = tid; idx < BM * BK / 4; idx += NTH) {
            int m = idx / (BK / 4);
            int kc = idx % (BK / 4);
            uint32_t dst = (uint32_t)__cvta_generic_to_shared(&sXb[m * XS + kc * 4]);
            int mm = (m < mrem) ? m : 0;
            const float* src = x + (size_t)(nb + mm) * K + k0 + kc * 4;
            cp_async16(dst, src, (m < mrem) ? 16 : 0);
        }
        for (int idx = tid; idx < BK * NC / 4; idx += NTH) {
            int kr = idx / (NC / 4);
            int j = (idx % (NC / 4)) * 4;
            const float* src = (j < F) ? (wl + (size_t)(kr + k0) * F + j)
                                       : (wr + (size_t)(kr + k0) * F + (j - F));
            uint32_t dst = (uint32_t)__cvta_generic_to_shared(&sBb[kr * NC + j]);
            cp_async16(dst, src, 16);
        }
    };

    load_tile(0, 0);
    cp_commit();

    constexpr int CG = NC / 8;
    const int tj = tid % CG;
    const int ti = tid / CG;
    const int m0 = ti * TM;
    const int jA = tj * 4;
    const int jB = jA + F;

    unsigned long long acc[TM][4];
#pragma unroll
    for (int i = 0; i < TM; ++i)
#pragma unroll
        for (int t = 0; t < 4; ++t) acc[i][t] = 0ull;

    for (int kb = 0; kb < KT; ++kb) {
        if (kb + 1 < KT) {
            load_tile(kb + 1, (kb + 1) & 1);
            cp_commit();
            cp_wait<1>();
        } else {
            cp_wait<0>();
        }
        __syncthreads();

        const float* bx = sX + (kb & 1) * BM * XS;
        const float* bb = sB + (kb & 1) * BK * NC;
#pragma unroll
        for (int k = 0; k < BK; ++k) {
            ulonglong2 bp0 = *reinterpret_cast<const ulonglong2*>(&bb[k * NC + jA]);
            ulonglong2 bp1 = *reinterpret_cast<const ulonglong2*>(&bb[k * NC + jB]);
#pragma unroll
            for (int i = 0; i < TM; ++i) {
                unsigned long long a2 = dup_f32(bx[(m0 + i) * XS + k]);
                fma_x2(acc[i][0], a2, bp0.x);
                fma_x2(acc[i][1], a2, bp0.y);
                fma_x2(acc[i][2], a2, bp1.x);
                fma_x2(acc[i][3], a2, bp1.y);
            }
        }
        __syncthreads();
    }

#pragma unroll
    for (int i = 0; i < TM; ++i) {
        int node = nb + m0 + i;
        if (node < n) {
            ulonglong2 v0, v1;
            v0.x = acc[i][0]; v0.y = acc[i][1];
            v1.x = acc[i][2]; v1.y = acc[i][3];
            *reinterpret_cast<ulonglong2*>(&ylr[(size_t)node * NC + jA]) = v0;
            *reinterpret_cast<ulonglong2*>(&ylr[(size_t)node * NC + jB]) = v1;
        }
    }
}

// ---------------------------------------------------------------------------
// per-node projection for small layers
// ---------------------------------------------------------------------------
template <int K, int F>
__global__ void proj_pernode(const float* __restrict__ x, const float* __restrict__ wl,
                             const float* __restrict__ wr, float* __restrict__ ylr, int n) {
    constexpr int NC = 2 * F;
    __shared__ float sB[K * NC];
    for (int i = threadIdx.x; i < K * NC; i += blockDim.x) {
        int k = i / NC, j = i % NC;
        sB[i] = (j < F) ? wl[k * F + j] : wr[k * F + (j - F)];
    }
    __syncthreads();

    int node = blockIdx.x * blockDim.x + threadIdx.x;
    if (node >= n) return;

    float xv[K];
    const float4* xr = reinterpret_cast<const float4*>(x + (size_t)node * K);
#pragma unroll
    for (int c = 0; c < K / 4; ++c) {
        float4 v = xr[c];
        xv[c * 4 + 0] = v.x; xv[c * 4 + 1] = v.y; xv[c * 4 + 2] = v.z; xv[c * 4 + 3] = v.w;
    }
    float acc[NC];
#pragma unroll
    for (int j = 0; j < NC; ++j) acc[j] = 0.f;
#pragma unroll
    for (int k = 0; k < K; ++k) {
        float a = xv[k];
#pragma unroll
        for (int j = 0; j < NC; ++j) acc[j] = fmaf(a, sB[k * NC + j], acc[j]);
    }
    float4* o = reinterpret_cast<float4*>(ylr + (size_t)node * NC);
#pragma unroll
    for (int c = 0; c < NC / 4; ++c)
        o[c] = make_float4(acc[c * 4], acc[c * 4 + 1], acc[c * 4 + 2], acc[c * 4 + 3]);
}

// layer 3 projection: K=16 -> 9+9, padded layout: node stride 32 floats
__global__ void proj3_pernode(const float* __restrict__ x, const float* __restrict__ wl,
                              const float* __restrict__ wr, float* __restrict__ ylr3, int n) {
    __shared__ float swl[16 * 9];
    __shared__ float swr[16 * 9];
    for (int i = threadIdx.x; i < 144; i += blockDim.x) {
        swl[i] = wl[i];
        swr[i] = wr[i];
    }
    __syncthreads();

    int node = blockIdx.x * blockDim.x + threadIdx.x;
    if (node >= n) return;

    float xv[16];
    const float4* xr = reinterpret_cast<const float4*>(x + (size_t)node * 16);
#pragma unroll
    for (int c = 0; c < 4; ++c) {
        float4 v = xr[c];
        xv[c * 4 + 0] = v.x; xv[c * 4 + 1] = v.y; xv[c * 4 + 2] = v.z; xv[c * 4 + 3] = v.w;
    }
    float al[9], ar[9];
#pragma unroll
    for (int j = 0; j < 9; ++j) { al[j] = 0.f; ar[j] = 0.f; }
#pragma unroll
    for (int k = 0; k < 16; ++k) {
        float a = xv[k];
#pragma unroll
        for (int j = 0; j < 9; ++j) {
            al[j] = fmaf(a, swl[k * 9 + j], al[j]);
            ar[j] = fmaf(a, swr[k * 9 + j], ar[j]);
        }
    }
    float4* o = reinterpret_cast<float4*>(ylr3 + (size_t)node * 32);
    o[0] = make_float4(al[0], al[1], al[2], al[3]);
    o[1] = make_float4(al[4], al[5], al[6], al[7]);
    o[2] = make_float4(al[8], 0.f, 0.f, 0.f);
    o[3] = make_float4(0.f, 0.f, 0.f, 0.f);
    o[4] = make_float4(ar[0], ar[1], ar[2], ar[3]);
    o[5] = make_float4(ar[4], ar[5], ar[6], ar[7]);
    ylr3[(size_t)node * 32 + 24] = ar[8];
}

// ---------------------------------------------------------------------------
// gather + combine (fused): warp per node.
// ---------------------------------------------------------------------------
template <int F, bool RELU>
__global__ void gather_combine(const float* __restrict__ ylr, const int* __restrict__ esrc,
                               const int* __restrict__ off, const int* __restrict__ cnt,
                               const float* __restrict__ bias, float* __restrict__ out, int n) {
    constexpr int CH = F / 4;
    constexpr int EPW = 32 / CH;
    int w = (blockIdx.x * blockDim.x + threadIdx.x) >> 5;
    if (w >= n) return;
    int lane = threadIdx.x & 31;
    int c = lane % CH, g = lane / CH;
    int start = off[w], deg = cnt[w];

    float4 acc = make_float4(0.f, 0.f, 0.f, 0.f);
    const float4* y4 = reinterpret_cast<const float4*>(ylr);
    for (int j = g; j < deg; j += EPW) {
        int s = __ldg(esrc + start + j);
        float4 v = y4[(size_t)s * (F / 2) + c];
        acc.x += v.x; acc.y += v.y; acc.z += v.z; acc.w += v.w;
    }
#pragma unroll
    for (int st = 16; st >= CH; st >>= 1) {
        acc.x += __shfl_xor_sync(0xFFFFFFFFu, acc.x, st);
        acc.y += __shfl_xor_sync(0xFFFFFFFFu, acc.y, st);
        acc.z += __shfl_xor_sync(0xFFFFFFFFu, acc.z, st);
        acc.w += __shfl_xor_sync(0xFFFFFFFFu, acc.w, st);
    }
    if (lane < CH) {
        float iv = __frcp_rn(fmaxf((float)deg, 1.0f));
        float4 r = y4[(size_t)w * (F / 2) + (F / 4) + c];
        float4 b = reinterpret_cast<const float4*>(bias)[c];
        float4 v;
        v.x = fmaf(acc.x, iv, r.x) + b.x;
        v.y = fmaf(acc.y, iv, r.y) + b.y;
        v.z = fmaf(acc.z, iv, r.z) + b.z;
        v.w = fmaf(acc.w, iv, r.w) + b.w;
        if (RELU) {
            v.x = fmaxf(v.x, 0.f); v.y = fmaxf(v.y, 0.f);
            v.z = fmaxf(v.z, 0.f); v.w = fmaxf(v.w, 0.f);
        }
        reinterpret_cast<float4*>(out)[(size_t)w * CH + c] = v;
    }
}

// final layer gather: padded yl (16-wide, stride 32), 9 outputs, no relu
__global__ void gather9(const float* __restrict__ ylr3, const int* __restrict__ esrc,
                        const int* __restrict__ off, const int* __restrict__ cnt,
                        const float* __restrict__ bias, float* __restrict__ out, int n) {
    int w = (blockIdx.x * blockDim.x + threadIdx.x) >> 5;
    if (w >= n) return;
    int lane = threadIdx.x & 31;
    int c = lane % 4, g = lane / 4;
    int start = off[w], deg = cnt[w];

    float4 acc = make_float4(0.f, 0.f, 0.f, 0.f);
    const float4* y4 = reinterpret_cast<const float4*>(ylr3);
    for (int j = g; j < deg; j += 8) {
        int s = __ldg(esrc + start + j);
        float4 v = y4[(size_t)s * 8 + c];
        acc.x += v.x; acc.y += v.y; acc.z += v.z; acc.w += v.w;
    }
#pragma unroll
    for (int st = 16; st >= 4; st >>= 1) {
        acc.x += __shfl_xor_sync(0xFFFFFFFFu, acc.x, st);
        acc.y += __shfl_xor_sync(0xFFFFFFFFu, acc.y, st);
        acc.z += __shfl_xor_sync(0xFFFFFFFFu, acc.z, st);
        acc.w += __shfl_xor_sync(0xFFFFFFFFu, acc.w, st);
    }
    if (lane < 4) {
        float iv = __frcp_rn(fmaxf((float)deg, 1.0f));
        float a[4] = {acc.x, acc.y, acc.z, acc.w};
#pragma unroll
        for (int t = 0; t < 4; ++t) {
            int j = c * 4 + t;
            if (j < 9) {
                float yr = ylr3[(size_t)w * 32 + 16 + j];
                out[(size_t)w * 9 + j] = fmaf(a[t], iv, yr + __ldg(bias + j));
            }
        }
    }
}

// ---------------------------------------------------------------------------
// launch — CSR build forked onto a side stream, overlapping the layer-0 GEMM
// ---------------------------------------------------------------------------
extern "C" void kernel_launch(void* const* d_in, const int* in_sizes, int n_in,
                              void* d_out, int out_size) {
    const float* emb = (const float*)d_in[0];
    const int* ei = (const int*)d_in[1];
    // d_in[2] = edge_attr, unused by SAGEConv
    const float* wl0 = (const float*)d_in[3];
    const float* wr0 = (const float*)d_in[4];
    const float* b0  = (const float*)d_in[5];
    const float* wl1 = (const float*)d_in[6];
    const float* wr1 = (const float*)d_in[7];
    const float* b1  = (const float*)d_in[8];
    const float* wl2 = (const float*)d_in[9];
    const float* wr2 = (const float*)d_in[10];
    const float* b2  = (const float*)d_in[11];
    const float* wl3 = (const float*)d_in[12];
    const float* wr3 = (const float*)d_in[13];
    const float* b3  = (const float*)d_in[14];
    float* out = (float*)d_out;

    const int n = in_sizes[0] / 128;
    const int E = in_sizes[1] / 2;
    const int* src = ei;
    const int* dst = ei + E;

    float *ylr, *xbuf;
    int *cnt, *off, *cur, *esrc, *bsum;
    cudaGetSymbolAddress((void**)&ylr, g_ylr);
    cudaGetSymbolAddress((void**)&xbuf, g_x);
    cudaGetSymbolAddress((void**)&cnt, g_cnt);
    cudaGetSymbolAddress((void**)&off, g_off);
    cudaGetSymbolAddress((void**)&cur, g_cur);
    cudaGetSymbolAddress((void**)&esrc, g_esrc);
    cudaGetSymbolAddress((void**)&bsum, g_bsum);

    auto cdiv = [](int a, int b) { return (a + b - 1) / b; };
    const int TB = 256;
    const int nb = cdiv(n, 512);

    const int SM0 = (2 * 64 * 36 + 2 * 32 * 128) * 4;   // 51200
    const int SM1 = (2 * 128 * 36 + 2 * 32 * 64) * 4;   // 53248
    cudaFuncSetAttribute((const void*)sgemm_proj_x2<128, 128, 64, 32, 4>,
                         cudaFuncAttributeMaxDynamicSharedMemorySize, SM0);
    cudaFuncSetAttribute((const void*)sgemm_proj_x2<64, 64, 128, 32, 4>,
                         cudaFuncAttributeMaxDynamicSharedMemorySize, SM1);

    // persistent side stream + events (created once; reused every call — same
    // work on every call, deterministic)
    static cudaStream_t s2 = nullptr;
    static cudaEvent_t evFork = nullptr, evJoin = nullptr;
    if (!s2) {
        cudaStreamCreateWithFlags(&s2, cudaStreamNonBlocking);
        cudaEventCreateWithFlags(&evFork, cudaEventDisableTiming);
        cudaEventCreateWithFlags(&evJoin, cudaEventDisableTiming);
    }

    // ---- fork: CSR build on s2, layer-0 GEMM on main stream ----
    cudaEventRecord(evFork, 0);
    cudaStreamWaitEvent(s2, evFork, 0);

    zero_int<<<cdiv(n, 512), 512, 0, s2>>>(cnt, n);
    hist_kernel<<<cdiv(E, 512), 512, 0, s2>>>(dst, cnt, E);
    scan_block<<<nb, 512, 0, s2>>>(cnt, off, bsum, n);
    scan_sums<<<1, 512, 0, s2>>>(bsum, nb);
    scan_add<<<nb, 512, 0, s2>>>(off, bsum, cur, n);
    fill_kernel<<<cdiv(E, 512), 512, 0, s2>>>(src, dst, cur, esrc, E);
    cudaEventRecord(evJoin, s2);

    sgemm_proj_x2<128, 128, 64, 32, 4><<<cdiv(n, 64), 128, SM0>>>(emb, wl0, wr0, ylr, n);

    // ---- join ----
    cudaStreamWaitEvent(0, evJoin, 0);

    // ---- layer 0 aggregation + remaining layers (serial chain) ----
    gather_combine<64, true><<<cdiv(n * 32, TB), TB>>>(ylr, esrc, off, cnt, b0, xbuf, n);

    sgemm_proj_x2<64, 64, 128, 32, 4><<<cdiv(n, 128), 128, SM1>>>(xbuf, wl1, wr1, ylr, n);
    gather_combine<32, true><<<cdiv(n * 32, TB), TB>>>(ylr, esrc, off, cnt, b1, xbuf, n);

    proj_pernode<32, 16><<<cdiv(n, TB), TB>>>(xbuf, wl2, wr2, ylr, n);
    gather_combine<16, true><<<cdiv(n * 32, TB), TB>>>(ylr, esrc, off, cnt, b2, xbuf, n);

    proj3_pernode<<<cdiv(n, TB), TB>>>(xbuf, wl3, wr3, ylr, n);
    gather9<<<cdiv(n * 32, TB), TB>>>(ylr, esrc, off, cnt, b3, out, n);
}